// round 7
// baseline (speedup 1.0000x reference)
#include <cuda_runtime.h>
#include <cuda_bf16.h>
#include <stdint.h>

// SimpleMovingAverage: history (64, 336, 862, 3) f32.
// window = last Q=12 steps; 336 iterations of m = mean(window), push m.
//
// Recurrence is linear: window state after T steps is A^T w0 with A fixed.
// Time is split into 7 chunks of 48 steps (48 = 4*12 keeps the register ring
// buffer statically indexed). Chunk c computes its starting window directly
// from the 12 input values via the precomputed matrix A^(48c).
//
// R5 lesson: coefficient __ldg's added ~1.1M L1 wavefronts and choked the
// store path. Fix: matrices are computed at COMPILE TIME (constexpr) into
// __constant__ memory -> constant-port loads, zero L1tex traffic, no init
// kernel. Chunk index is a template parameter so all coefficient indices are
// compile-time. Plain STG (R4's best-performing store config).
//
// Per-step critical path: 1 FFMA:  m = s/12;  s = fma(s, 13/12, -w[u]).

#define SMA_Q       12
#define SMA_INLEN   336
#define SMA_OUTLEN  336
#define SMA_ROW     2586          // 862 * 3 floats, contiguous
#define SMA_ROW2    (SMA_ROW / 2) // 1293 float2 per row
#define SMA_BATCH   64
#define SMA_NTHREADS (SMA_BATCH * SMA_ROW2)  // 82752 float2-series

#define SMA_CHUNKS  7
#define SMA_CSTEPS  (SMA_OUTLEN / SMA_CHUNKS)  // 48 = 4 * 12

struct SmaMats {
    // m[c][k][slot]: coefficient of initial-window element k in window slot
    // `slot` after 48*(c+1) steps of the recurrence.
    float m[SMA_CHUNKS - 1][SMA_Q][SMA_Q];
};

static constexpr SmaMats sma_compute_mats() {
    SmaMats r = {};
    for (int k = 0; k < SMA_Q; k++) {
        float w[SMA_Q] = {};
        for (int i = 0; i < SMA_Q; i++) w[i] = (i == k) ? 1.0f : 0.0f;
        float s = 1.0f;
        for (int c = 0; c < SMA_CHUNKS - 1; c++) {
            for (int t = 0; t < SMA_CSTEPS; t++) {
                int u = t % SMA_Q;
                float mean = s * (1.0f / 12.0f);
                s = s * (13.0f / 12.0f) - w[u];
                w[u] = mean;
            }
            for (int j = 0; j < SMA_Q; j++) r.m[c][k][j] = w[j];
        }
    }
    return r;
}

__constant__ SmaMats c_MATS = sma_compute_mats();

template <int CHUNK>
__device__ __forceinline__ void sma_run_chunk(
    const float2* __restrict__ src, float2* __restrict__ dst)
{
    float wx[SMA_Q], wy[SMA_Q];
    float sx = 0.0f, sy = 0.0f;

    if (CHUNK == 0) {
#pragma unroll
        for (int k = 0; k < SMA_Q; k++) {
            float2 v = src[(size_t)k * SMA_ROW2];
            wx[k] = v.x; wy[k] = v.y;
            sx += v.x;   sy += v.y;
        }
    } else {
#pragma unroll
        for (int j = 0; j < SMA_Q; j++) { wx[j] = 0.0f; wy[j] = 0.0f; }
        // Streamed matvec; coefficients come from the constant port (no L1).
#pragma unroll
        for (int k = 0; k < SMA_Q; k++) {
            float2 v = src[(size_t)k * SMA_ROW2];
#pragma unroll
            for (int j = 0; j < SMA_Q; j++) {
                float c = c_MATS.m[CHUNK - 1][k][j];
                wx[j] = fmaf(c, v.x, wx[j]);
                wy[j] = fmaf(c, v.y, wy[j]);
            }
        }
#pragma unroll
        for (int j = 0; j < SMA_Q; j++) { sx += wx[j]; sy += wy[j]; }
    }

    const float inv_q = 1.0f / 12.0f;
    const float k1312 = 13.0f / 12.0f;

    float2* d = dst;
#pragma unroll 1
    for (int blk = 0; blk < SMA_CSTEPS / SMA_Q; blk++) {
#pragma unroll
        for (int u = 0; u < SMA_Q; u++) {
            float mx = sx * inv_q;
            float my = sy * inv_q;
            d[(size_t)u * SMA_ROW2] = make_float2(mx, my);
            sx = fmaf(sx, k1312, -wx[u]);
            sy = fmaf(sy, k1312, -wy[u]);
            wx[u] = mx;
            wy[u] = my;
        }
        d += (size_t)SMA_Q * SMA_ROW2;
    }
}

__global__ __launch_bounds__(128)
void sma_main_kernel(const float* __restrict__ in, float* __restrict__ out) {
    int id = blockIdx.x * blockDim.x + threadIdx.x;
    if (id >= SMA_NTHREADS) return;
    int chunk = blockIdx.y;

    int b  = id / SMA_ROW2;
    int j2 = id - b * SMA_ROW2;

    const float2* __restrict__ src =
        reinterpret_cast<const float2*>(
            in + (size_t)b * SMA_INLEN * SMA_ROW
               + (size_t)(SMA_INLEN - SMA_Q) * SMA_ROW) + j2;
    float2* __restrict__ dst =
        reinterpret_cast<float2*>(out + (size_t)b * SMA_OUTLEN * SMA_ROW
                                      + (size_t)chunk * SMA_CSTEPS * SMA_ROW) + j2;

    switch (chunk) {
        case 0: sma_run_chunk<0>(src, dst); break;
        case 1: sma_run_chunk<1>(src, dst); break;
        case 2: sma_run_chunk<2>(src, dst); break;
        case 3: sma_run_chunk<3>(src, dst); break;
        case 4: sma_run_chunk<4>(src, dst); break;
        case 5: sma_run_chunk<5>(src, dst); break;
        case 6: sma_run_chunk<6>(src, dst); break;
        default: break;
    }
}

extern "C" void kernel_launch(void* const* d_in, const int* in_sizes, int n_in,
                              void* d_out, int out_size) {
    (void)in_sizes; (void)n_in; (void)out_size;
    const float* in = (const float*)d_in[0];
    float* out = (float*)d_out;

    const int threads = 128;
    const int blocks = (SMA_NTHREADS + threads - 1) / threads;  // 647
    dim3 grid(blocks, SMA_CHUNKS);
    sma_main_kernel<<<grid, threads>>>(in, out);
}